// round 1
// baseline (speedup 1.0000x reference)
#include <cuda_runtime.h>
#include <math.h>

#define NN 100000
#define NE 1600000
#define NG 1024
#define FD 128
#define NCHUNK 1563          // ceil(NN/64)
#define GRIDP 152            // GB300 SM count; 1 block/SM (smem-limited)

// ---------------- scratch (device globals; no allocs allowed) ----------------
__device__ float g_h[NN * FD];
__device__ float g_agg[NN * FD];
__device__ float g_y1[NN * FD];
__device__ float g_degf[NN];
__device__ int   g_deg[NN];
__device__ int   g_rowstart[NN + 1];
__device__ int   g_cursor[NN];
__device__ int   g_csrsrc[NE];
__device__ int   g_cnti[NG];
__device__ float g_cntf[NG];
__device__ float g_gm[NG * FD];
__device__ float g_gw[NG * FD];
__device__ float g_p[NG * FD];
__device__ float g_Wc[FD * FD];
__device__ int   g_bsum[256];

// ---------------- setup kernels ----------------
__global__ void k_zero() {
    int i = blockIdx.x * blockDim.x + threadIdx.x;
    if (i < NN) g_deg[i] = 0;
    if (i < NG) g_cnti[i] = 0;
    if (i < NG * FD) { g_gm[i] = 0.f; g_p[i] = 0.f; }
}

__global__ void k_count(const int* __restrict__ ei, const int* __restrict__ batch) {
    int i = blockIdx.x * blockDim.x + threadIdx.x;
    if (i < NE) atomicAdd(&g_deg[ei[NE + i]], 1);
    if (i < NN) atomicAdd(&g_cnti[batch[i]], 1);
}

__global__ void k_scan1() {
    __shared__ int s[512];
    int i = blockIdx.x * 512 + threadIdx.x;
    int v = (i < NN) ? g_deg[i] : 0;
    s[threadIdx.x] = v;
    __syncthreads();
#pragma unroll
    for (int off = 1; off < 512; off <<= 1) {
        int t = (threadIdx.x >= off) ? s[threadIdx.x - off] : 0;
        __syncthreads();
        s[threadIdx.x] += t;
        __syncthreads();
    }
    if (i < NN) g_rowstart[i + 1] = s[threadIdx.x];
    if (threadIdx.x == 511) g_bsum[blockIdx.x] = s[511];
}

__global__ void k_scan2() {
    __shared__ int s[256];
    const int nb = (NN + 511) / 512;  // 196
    int v = (threadIdx.x < nb) ? g_bsum[threadIdx.x] : 0;
    s[threadIdx.x] = v;
    __syncthreads();
#pragma unroll
    for (int off = 1; off < 256; off <<= 1) {
        int t = (threadIdx.x >= off) ? s[threadIdx.x - off] : 0;
        __syncthreads();
        s[threadIdx.x] += t;
        __syncthreads();
    }
    g_bsum[threadIdx.x] = s[threadIdx.x] - v;  // exclusive
}

__global__ void k_scan3() {
    int i = blockIdx.x * blockDim.x + threadIdx.x;
    if (i >= NN) return;
    int r = g_rowstart[i + 1] + g_bsum[i >> 9];
    g_rowstart[i + 1] = r;
    g_cursor[i] = r - g_deg[i];
    g_degf[i] = fmaxf((float)g_deg[i], 1.f);
    if (i == 0) g_rowstart[0] = 0;
    if (i < NG) g_cntf[i] = fmaxf((float)g_cnti[i], 1.f);
}

__global__ void k_fill(const int* __restrict__ ei) {
    int e = blockIdx.x * blockDim.x + threadIdx.x;
    if (e >= NE) return;
    int src = ei[e];
    int dst = ei[NE + e];
    int pos = atomicAdd(&g_cursor[dst], 1);
    g_csrsrc[pos] = src;
}

// ---------------- gather: agg[n] = mean over incoming edges of h[src] ----------------
__global__ void k_gather() {
    int gw = (blockIdx.x * blockDim.x + threadIdx.x) >> 5;
    int lane = threadIdx.x & 31;
    if (gw >= NN) return;
    int beg = g_rowstart[gw], end = g_rowstart[gw + 1];
    float4 acc = make_float4(0.f, 0.f, 0.f, 0.f);
    const float4* hv = (const float4*)g_h;
    int e = beg;
    for (; e + 4 <= end; e += 4) {
        int s0 = g_csrsrc[e], s1 = g_csrsrc[e + 1], s2 = g_csrsrc[e + 2], s3 = g_csrsrc[e + 3];
        float4 a0 = hv[s0 * 32 + lane];
        float4 a1 = hv[s1 * 32 + lane];
        float4 a2 = hv[s2 * 32 + lane];
        float4 a3 = hv[s3 * 32 + lane];
        acc.x += (a0.x + a1.x) + (a2.x + a3.x);
        acc.y += (a0.y + a1.y) + (a2.y + a3.y);
        acc.z += (a0.z + a1.z) + (a2.z + a3.z);
        acc.w += (a0.w + a1.w) + (a2.w + a3.w);
    }
    for (; e < end; ++e) {
        int s0 = g_csrsrc[e];
        float4 a0 = hv[s0 * 32 + lane];
        acc.x += a0.x; acc.y += a0.y; acc.z += a0.z; acc.w += a0.w;
    }
    float inv = 1.f / g_degf[gw];
    acc.x *= inv; acc.y *= inv; acc.z *= inv; acc.w *= inv;
    ((float4*)g_agg)[gw * 32 + lane] = acc;
}

// ---------------- input linear: h = [x|w] @ W_in + b_in ----------------
__global__ void __launch_bounds__(256, 1) k_input(
    const float* __restrict__ x, const float* __restrict__ w,
    const float* __restrict__ Win, const float* __restrict__ bin) {
    extern __shared__ float sm[];
    float* W_s = sm;                 // 129*128 = 16512
    float* xs = sm + 16512;          // 64*128 = 8192
    float* ws = sm + 16512 + 8192;   // 64
    __shared__ float b_s[128];
    for (int i = threadIdx.x; i < 4128; i += 256)
        ((float4*)W_s)[i] = ((const float4*)Win)[i];
    if (threadIdx.x < 128) b_s[threadIdx.x] = bin[threadIdx.x];

    int lane = threadIdx.x & 31;
    int wp = threadIdx.x >> 5;

    for (int cb = blockIdx.x; cb < NCHUNK; cb += gridDim.x) {
        int nbase = cb * 64;
        __syncthreads();
        for (int i = threadIdx.x; i < 2048; i += 256) {
            int gi = nbase + (i >> 5);
            float4 v = make_float4(0.f, 0.f, 0.f, 0.f);
            if (gi < NN) v = ((const float4*)x)[gi * 32 + (i & 31)];
            ((float4*)xs)[i] = v;
        }
        if (threadIdx.x < 64) {
            int gi = nbase + threadIdx.x;
            ws[threadIdx.x] = (gi < NN) ? w[gi] : 0.f;
        }
        __syncthreads();

        float acc[8][4];
#pragma unroll
        for (int n = 0; n < 8; n++) { acc[n][0] = acc[n][1] = acc[n][2] = acc[n][3] = 0.f; }
        const float* is = xs + wp * 1024;
#pragma unroll 2
        for (int k = 0; k < 128; k++) {
            float4 wv = ((const float4*)(W_s + k * 128))[lane];
#pragma unroll
            for (int n = 0; n < 8; n++) {
                float a = is[n * 128 + k];
                acc[n][0] = fmaf(a, wv.x, acc[n][0]);
                acc[n][1] = fmaf(a, wv.y, acc[n][1]);
                acc[n][2] = fmaf(a, wv.z, acc[n][2]);
                acc[n][3] = fmaf(a, wv.w, acc[n][3]);
            }
        }
        float4 wlast = ((const float4*)(W_s + 128 * 128))[lane];
        float4 bv = ((const float4*)b_s)[lane];
#pragma unroll
        for (int n = 0; n < 8; n++) {
            int node = nbase + wp * 8 + n;
            float a = ws[wp * 8 + n];
            float4 o;
            o.x = acc[n][0] + a * wlast.x + bv.x;
            o.y = acc[n][1] + a * wlast.y + bv.y;
            o.z = acc[n][2] + a * wlast.z + bv.z;
            o.w = acc[n][3] + a * wlast.w + bv.w;
            if (node < NN) ((float4*)g_h)[node * 32 + lane] = o;
        }
    }
}

// ---------------- SAGE: y1 = LN(agg@Wl + bl + h@Wr + h) ----------------
__global__ void __launch_bounds__(256, 1) k_sage(
    const float* __restrict__ Wl, const float* __restrict__ bl,
    const float* __restrict__ Wr,
    const float* __restrict__ lng, const float* __restrict__ lnb) {
    extern __shared__ float sm[];
    float* Wl_s = sm;            // 16384
    float* Wr_s = sm + 16384;    // 16384
    float* agg_s = sm + 32768;   // 8192
    float* h_s = sm + 40960;     // 8192
    __shared__ float bl_s[128], g_s[128], e_s[128];
    for (int i = threadIdx.x; i < 4096; i += 256) {
        ((float4*)Wl_s)[i] = ((const float4*)Wl)[i];
        ((float4*)Wr_s)[i] = ((const float4*)Wr)[i];
    }
    if (threadIdx.x < 128) {
        bl_s[threadIdx.x] = bl[threadIdx.x];
        g_s[threadIdx.x] = lng[threadIdx.x];
        e_s[threadIdx.x] = lnb[threadIdx.x];
    }
    int lane = threadIdx.x & 31;
    int wp = threadIdx.x >> 5;

    for (int cb = blockIdx.x; cb < NCHUNK; cb += gridDim.x) {
        int nbase = cb * 64;
        __syncthreads();
        for (int i = threadIdx.x; i < 2048; i += 256) {
            int gi = nbase + (i >> 5);
            float4 va = make_float4(0.f, 0.f, 0.f, 0.f), vh = va;
            if (gi < NN) {
                va = ((const float4*)g_agg)[gi * 32 + (i & 31)];
                vh = ((const float4*)g_h)[gi * 32 + (i & 31)];
            }
            ((float4*)agg_s)[i] = va;
            ((float4*)h_s)[i] = vh;
        }
        __syncthreads();

        float acc[8][4];
#pragma unroll
        for (int n = 0; n < 8; n++) { acc[n][0] = acc[n][1] = acc[n][2] = acc[n][3] = 0.f; }
        const float* as = agg_s + wp * 1024;
        const float* hs = h_s + wp * 1024;
#pragma unroll 2
        for (int k = 0; k < 128; k++) {
            float4 wl = ((const float4*)(Wl_s + k * 128))[lane];
            float4 wr = ((const float4*)(Wr_s + k * 128))[lane];
#pragma unroll
            for (int n = 0; n < 8; n++) {
                float a = as[n * 128 + k];
                float h = hs[n * 128 + k];
                acc[n][0] = fmaf(a, wl.x, fmaf(h, wr.x, acc[n][0]));
                acc[n][1] = fmaf(a, wl.y, fmaf(h, wr.y, acc[n][1]));
                acc[n][2] = fmaf(a, wl.z, fmaf(h, wr.z, acc[n][2]));
                acc[n][3] = fmaf(a, wl.w, fmaf(h, wr.w, acc[n][3]));
            }
        }
        float4 bv = ((const float4*)bl_s)[lane];
        float4 gv = ((const float4*)g_s)[lane];
        float4 ev = ((const float4*)e_s)[lane];
#pragma unroll
        for (int n = 0; n < 8; n++) {
            int node = nbase + wp * 8 + n;
            float v0 = acc[n][0] + bv.x + hs[n * 128 + lane * 4 + 0];
            float v1 = acc[n][1] + bv.y + hs[n * 128 + lane * 4 + 1];
            float v2 = acc[n][2] + bv.z + hs[n * 128 + lane * 4 + 2];
            float v3 = acc[n][3] + bv.w + hs[n * 128 + lane * 4 + 3];
            float s = v0 + v1 + v2 + v3;
            float q = v0 * v0 + v1 * v1 + v2 * v2 + v3 * v3;
#pragma unroll
            for (int off = 16; off; off >>= 1) {
                s += __shfl_xor_sync(0xffffffffu, s, off);
                q += __shfl_xor_sync(0xffffffffu, q, off);
            }
            float mu = s * 0.0078125f;
            float var = q * 0.0078125f - mu * mu;
            float inv = rsqrtf(var + 1e-5f);
            if (node < NN) {
                float4 o;
                o.x = (v0 - mu) * inv * gv.x + ev.x;
                o.y = (v1 - mu) * inv * gv.y + ev.y;
                o.z = (v2 - mu) * inv * gv.z + ev.z;
                o.w = (v3 - mu) * inv * gv.w + ev.w;
                ((float4*)g_y1)[node * 32 + lane] = o;
            }
        }
    }
}

// ---------------- FFN: h = LN(elu(y1@W1+b1)@W2 + b2 + y1) ----------------
__global__ void __launch_bounds__(256, 1) k_ffn(
    const float* __restrict__ W1, const float* __restrict__ b1,
    const float* __restrict__ W2, const float* __restrict__ b2,
    const float* __restrict__ lng, const float* __restrict__ lnb) {
    extern __shared__ float sm[];
    float* W1_s = sm;
    float* W2_s = sm + 16384;
    float* y_s = sm + 32768;
    float* t_s = sm + 40960;
    __shared__ float b1_s[128], b2_s[128], g_s[128], e_s[128];
    for (int i = threadIdx.x; i < 4096; i += 256) {
        ((float4*)W1_s)[i] = ((const float4*)W1)[i];
        ((float4*)W2_s)[i] = ((const float4*)W2)[i];
    }
    if (threadIdx.x < 128) {
        b1_s[threadIdx.x] = b1[threadIdx.x];
        b2_s[threadIdx.x] = b2[threadIdx.x];
        g_s[threadIdx.x] = lng[threadIdx.x];
        e_s[threadIdx.x] = lnb[threadIdx.x];
    }
    int lane = threadIdx.x & 31;
    int wp = threadIdx.x >> 5;

    for (int cb = blockIdx.x; cb < NCHUNK; cb += gridDim.x) {
        int nbase = cb * 64;
        __syncthreads();
        for (int i = threadIdx.x; i < 2048; i += 256) {
            int gi = nbase + (i >> 5);
            float4 v = make_float4(0.f, 0.f, 0.f, 0.f);
            if (gi < NN) v = ((const float4*)g_y1)[gi * 32 + (i & 31)];
            ((float4*)y_s)[i] = v;
        }
        __syncthreads();

        float acc[8][4];
#pragma unroll
        for (int n = 0; n < 8; n++) { acc[n][0] = acc[n][1] = acc[n][2] = acc[n][3] = 0.f; }
        const float* ys = y_s + wp * 1024;
        float* ts = t_s + wp * 1024;
#pragma unroll 2
        for (int k = 0; k < 128; k++) {
            float4 wv = ((const float4*)(W1_s + k * 128))[lane];
#pragma unroll
            for (int n = 0; n < 8; n++) {
                float a = ys[n * 128 + k];
                acc[n][0] = fmaf(a, wv.x, acc[n][0]);
                acc[n][1] = fmaf(a, wv.y, acc[n][1]);
                acc[n][2] = fmaf(a, wv.z, acc[n][2]);
                acc[n][3] = fmaf(a, wv.w, acc[n][3]);
            }
        }
        float4 b1v = ((const float4*)b1_s)[lane];
#pragma unroll
        for (int n = 0; n < 8; n++) {
            float t0 = acc[n][0] + b1v.x; t0 = t0 > 0.f ? t0 : expm1f(t0);
            float t1 = acc[n][1] + b1v.y; t1 = t1 > 0.f ? t1 : expm1f(t1);
            float t2 = acc[n][2] + b1v.z; t2 = t2 > 0.f ? t2 : expm1f(t2);
            float t3 = acc[n][3] + b1v.w; t3 = t3 > 0.f ? t3 : expm1f(t3);
            ((float4*)(ts + n * 128))[lane] = make_float4(t0, t1, t2, t3);
        }
        __syncwarp();
#pragma unroll
        for (int n = 0; n < 8; n++) { acc[n][0] = acc[n][1] = acc[n][2] = acc[n][3] = 0.f; }
#pragma unroll 2
        for (int k = 0; k < 128; k++) {
            float4 wv = ((const float4*)(W2_s + k * 128))[lane];
#pragma unroll
            for (int n = 0; n < 8; n++) {
                float a = ts[n * 128 + k];
                acc[n][0] = fmaf(a, wv.x, acc[n][0]);
                acc[n][1] = fmaf(a, wv.y, acc[n][1]);
                acc[n][2] = fmaf(a, wv.z, acc[n][2]);
                acc[n][3] = fmaf(a, wv.w, acc[n][3]);
            }
        }
        float4 b2v = ((const float4*)b2_s)[lane];
        float4 gv = ((const float4*)g_s)[lane];
        float4 ev = ((const float4*)e_s)[lane];
#pragma unroll
        for (int n = 0; n < 8; n++) {
            int node = nbase + wp * 8 + n;
            float v0 = acc[n][0] + b2v.x + ys[n * 128 + lane * 4 + 0];
            float v1 = acc[n][1] + b2v.y + ys[n * 128 + lane * 4 + 1];
            float v2 = acc[n][2] + b2v.z + ys[n * 128 + lane * 4 + 2];
            float v3 = acc[n][3] + b2v.w + ys[n * 128 + lane * 4 + 3];
            float s = v0 + v1 + v2 + v3;
            float q = v0 * v0 + v1 * v1 + v2 * v2 + v3 * v3;
#pragma unroll
            for (int off = 16; off; off >>= 1) {
                s += __shfl_xor_sync(0xffffffffu, s, off);
                q += __shfl_xor_sync(0xffffffffu, q, off);
            }
            float mu = s * 0.0078125f;
            float var = q * 0.0078125f - mu * mu;
            float inv = rsqrtf(var + 1e-5f);
            if (node < NN) {
                float4 o;
                o.x = (v0 - mu) * inv * gv.x + ev.x;
                o.y = (v1 - mu) * inv * gv.y + ev.y;
                o.z = (v2 - mu) * inv * gv.z + ev.z;
                o.w = (v3 - mu) * inv * gv.w + ev.w;
                ((float4*)g_h)[node * 32 + lane] = o;
            }
        }
    }
}

// ---------------- pooling accumulation ----------------
__global__ void k_gmacc(const int* __restrict__ batch) {
    int i = blockIdx.x * blockDim.x + threadIdx.x;
    if (i >= NN * FD) return;
    int n = i >> 7, f = i & 127;
    atomicAdd(&g_gm[batch[n] * FD + f], g_h[i]);
}
__global__ void k_pacc(const int* __restrict__ batch) {
    int i = blockIdx.x * blockDim.x + threadIdx.x;
    if (i >= NN * FD) return;
    int n = i >> 7, f = i & 127;
    atomicAdd(&g_p[batch[n] * FD + f], g_agg[i]);
}

// Wc = mdf_W[0:128] + mdf_W[128:256]
__global__ void k_wc(const float* __restrict__ mdfW) {
    int i = blockIdx.x * blockDim.x + threadIdx.x;
    if (i < FD * FD) g_Wc[i] = mdfW[i] + mdfW[FD * FD + i];
}

// gW = (gm/cnt) @ mdf_W_bottom
__global__ void k_gw(const float* __restrict__ mdfW) {
    __shared__ float s[128];
    int g = blockIdx.x, f = threadIdx.x;
    s[f] = g_gm[g * FD + f] / g_cntf[g];
    __syncthreads();
    const float* Wb = mdfW + FD * FD;
    float acc = 0.f;
#pragma unroll 4
    for (int k = 0; k < 128; k++) acc = fmaf(s[k], Wb[k * FD + f], acc);
    g_gw[g * FD + f] = acc;
}

// h2 = h @ Wc + mdf_b - gW[batch]   (writes g_agg)
__global__ void __launch_bounds__(256, 1) k_mdf(const float* __restrict__ mb,
                                                const int* __restrict__ batch) {
    extern __shared__ float sm[];
    float* W_s = sm;           // 16384
    float* h_s = sm + 16384;   // 8192
    __shared__ float b_s[128];
    __shared__ int bb_s[64];
    for (int i = threadIdx.x; i < 4096; i += 256)
        ((float4*)W_s)[i] = ((const float4*)g_Wc)[i];
    if (threadIdx.x < 128) b_s[threadIdx.x] = mb[threadIdx.x];

    int lane = threadIdx.x & 31;
    int wp = threadIdx.x >> 5;
    for (int cb = blockIdx.x; cb < NCHUNK; cb += gridDim.x) {
        int nbase = cb * 64;
        __syncthreads();
        for (int i = threadIdx.x; i < 2048; i += 256) {
            int gi = nbase + (i >> 5);
            float4 v = make_float4(0.f, 0.f, 0.f, 0.f);
            if (gi < NN) v = ((const float4*)g_h)[gi * 32 + (i & 31)];
            ((float4*)h_s)[i] = v;
        }
        if (threadIdx.x < 64) {
            int gi = nbase + threadIdx.x;
            bb_s[threadIdx.x] = (gi < NN) ? batch[gi] : 0;
        }
        __syncthreads();

        float acc[8][4];
#pragma unroll
        for (int n = 0; n < 8; n++) { acc[n][0] = acc[n][1] = acc[n][2] = acc[n][3] = 0.f; }
        const float* hs = h_s + wp * 1024;
#pragma unroll 2
        for (int k = 0; k < 128; k++) {
            float4 wv = ((const float4*)(W_s + k * 128))[lane];
#pragma unroll
            for (int n = 0; n < 8; n++) {
                float a = hs[n * 128 + k];
                acc[n][0] = fmaf(a, wv.x, acc[n][0]);
                acc[n][1] = fmaf(a, wv.y, acc[n][1]);
                acc[n][2] = fmaf(a, wv.z, acc[n][2]);
                acc[n][3] = fmaf(a, wv.w, acc[n][3]);
            }
        }
        float4 bv = ((const float4*)b_s)[lane];
#pragma unroll
        for (int n = 0; n < 8; n++) {
            int node = nbase + wp * 8 + n;
            if (node < NN) {
                int bg = bb_s[wp * 8 + n];
                float4 gwv = ((const float4*)g_gw)[bg * 32 + lane];
                float4 o;
                o.x = acc[n][0] + bv.x - gwv.x;
                o.y = acc[n][1] + bv.y - gwv.y;
                o.z = acc[n][2] + bv.z - gwv.z;
                o.w = acc[n][3] + bv.w - gwv.w;
                ((float4*)g_agg)[node * 32 + lane] = o;
            }
        }
    }
}

// ---------------- final per-graph MLP head ----------------
__global__ void k_pool(const float* __restrict__ pg1, const float* __restrict__ pb1,
                       const float* __restrict__ W1, const float* __restrict__ b1,
                       const float* __restrict__ W2, const float* __restrict__ b2,
                       const float* __restrict__ pg2, const float* __restrict__ pb2,
                       float* __restrict__ out) {
    __shared__ float hh[128], tt[128], red[8];
    int g = blockIdx.x, f = threadIdx.x;
    int lane = f & 31, wp = f >> 5;
    float v = g_p[g * FD + f] / g_cntf[g];

    float s = v, q = v * v;
#pragma unroll
    for (int off = 16; off; off >>= 1) {
        s += __shfl_xor_sync(0xffffffffu, s, off);
        q += __shfl_xor_sync(0xffffffffu, q, off);
    }
    if (lane == 0) { red[wp] = s; red[4 + wp] = q; }
    __syncthreads();
    s = red[0] + red[1] + red[2] + red[3];
    q = red[4] + red[5] + red[6] + red[7];
    float mu = s * 0.0078125f;
    float var = q * 0.0078125f - mu * mu;
    float inv = rsqrtf(var + 1e-5f);
    float h0 = (v - mu) * inv * pg1[f] + pb1[f];
    __syncthreads();
    hh[f] = h0;
    __syncthreads();

    float a = 0.f;
#pragma unroll 4
    for (int k = 0; k < 128; k++) a = fmaf(hh[k], W1[k * FD + f], a);
    a += b1[f];
    a = a > 0.f ? a : expm1f(a);
    tt[f] = a;
    __syncthreads();

    float y = 0.f;
#pragma unroll 4
    for (int k = 0; k < 128; k++) y = fmaf(tt[k], W2[k * FD + f], y);
    y += b2[f];
    float v2 = y + h0;

    s = v2; q = v2 * v2;
#pragma unroll
    for (int off = 16; off; off >>= 1) {
        s += __shfl_xor_sync(0xffffffffu, s, off);
        q += __shfl_xor_sync(0xffffffffu, q, off);
    }
    if (lane == 0) { red[wp] = s; red[4 + wp] = q; }
    __syncthreads();
    s = red[0] + red[1] + red[2] + red[3];
    q = red[4] + red[5] + red[6] + red[7];
    mu = s * 0.0078125f;
    var = q * 0.0078125f - mu * mu;
    inv = rsqrtf(var + 1e-5f);
    out[g * FD + f] = (v2 - mu) * inv * pg2[f] + pb2[f];
}

// ---------------- launcher ----------------
extern "C" void kernel_launch(void* const* d_in, const int* in_sizes, int n_in,
                              void* d_out, int out_size) {
    const float* x    = (const float*)d_in[0];
    const float* w    = (const float*)d_in[1];
    const int*   ei   = (const int*)d_in[2];
    const int*   batch= (const int*)d_in[3];
    const float* Win  = (const float*)d_in[4];
    const float* bin  = (const float*)d_in[5];
    const float* sWl  = (const float*)d_in[6];
    const float* sbl  = (const float*)d_in[7];
    const float* sWr  = (const float*)d_in[8];
    const float* ln1g = (const float*)d_in[9];
    const float* ln1b = (const float*)d_in[10];
    const float* l1W  = (const float*)d_in[11];
    const float* l1b  = (const float*)d_in[12];
    const float* l2W  = (const float*)d_in[13];
    const float* l2b  = (const float*)d_in[14];
    const float* ln2g = (const float*)d_in[15];
    const float* ln2b = (const float*)d_in[16];
    const float* mdfW = (const float*)d_in[17];
    const float* mdfb = (const float*)d_in[18];
    const float* pg1  = (const float*)d_in[19];
    const float* pb1  = (const float*)d_in[20];
    const float* pW1  = (const float*)d_in[21];
    const float* pb1l = (const float*)d_in[22];
    const float* pW2  = (const float*)d_in[23];
    const float* pb2l = (const float*)d_in[24];
    const float* pg2  = (const float*)d_in[25];
    const float* pb2  = (const float*)d_in[26];

    cudaFuncSetAttribute(k_input, cudaFuncAttributeMaxDynamicSharedMemorySize, 99072);
    cudaFuncSetAttribute(k_sage,  cudaFuncAttributeMaxDynamicSharedMemorySize, 196608);
    cudaFuncSetAttribute(k_ffn,   cudaFuncAttributeMaxDynamicSharedMemorySize, 196608);
    cudaFuncSetAttribute(k_mdf,   cudaFuncAttributeMaxDynamicSharedMemorySize, 98304);

    k_zero<<<512, 256>>>();
    k_count<<<(NE + 255) / 256, 256>>>(ei, batch);
    k_scan1<<<(NN + 511) / 512, 512>>>();
    k_scan2<<<1, 256>>>();
    k_scan3<<<(NN + 255) / 256, 256>>>();
    k_fill<<<(NE + 255) / 256, 256>>>(ei);

    k_input<<<GRIDP, 256, 99072>>>(x, w, Win, bin);

    for (int l = 0; l < 3; l++) {
        k_gather<<<(NN * 32) / 256, 256>>>();
        k_sage<<<GRIDP, 256, 196608>>>(sWl + l * FD * FD, sbl + l * FD,
                                       sWr + l * FD * FD, ln1g + l * FD, ln1b + l * FD);
        k_ffn<<<GRIDP, 256, 196608>>>(l1W + l * FD * FD, l1b + l * FD,
                                      l2W + l * FD * FD, l2b + l * FD,
                                      ln2g + l * FD, ln2b + l * FD);
    }

    k_gmacc<<<(NN * FD + 255) / 256, 256>>>(batch);
    k_wc<<<(FD * FD + 255) / 256, 256>>>(mdfW);
    k_gw<<<NG, 128>>>(mdfW);
    k_mdf<<<GRIDP, 256, 98304>>>(mdfb, batch);
    k_pacc<<<(NN * FD + 255) / 256, 256>>>(batch);
    k_pool<<<NG, 128>>>(pg1, pb1, pW1, pb1l, pW2, pb2l, pg2, pb2, (float*)d_out);
}

// round 3
// speedup vs baseline: 1.1215x; 1.1215x over previous
#include <cuda_runtime.h>
#include <cuda_bf16.h>
#include <math.h>
#include <stdint.h>

#define NN 100000
#define NE 1600000
#define NG 1024
#define FD 128
#define NTILE 782           // ceil(NN/128)

// ===================== scratch (device globals) =====================
__device__ float g_h[NN * FD];
__device__ float g_agg[NN * FD];
__device__ float g_y1[NN * FD];
__device__ float g_degf[NN];
__device__ int   g_deg[NN];
__device__ int   g_rowstart[NN + 1];
__device__ int   g_cursor[NN];
__device__ int   g_csrsrc[NE];
__device__ int   g_cnti[NG];
__device__ float g_cntf[NG];
__device__ float g_gm[NG * FD];
__device__ float g_gw[NG * FD];
__device__ float g_p[NG * FD];
__device__ float g_Wc[FD * FD];
__device__ int   g_bsum[256];
// pre-transposed, split, swizzled weights: 14 matrices of 128x128 bf16
// m: 0=Win, 1..3=sage_Wl, 4..6=sage_Wr, 7..9=lin1, 10..12=lin2, 13=Wc
__device__ __nv_bfloat16 g_whi[14 * 16384];
__device__ __nv_bfloat16 g_wlo[14 * 16384];

// ===================== helpers =====================
__device__ __forceinline__ uint32_t smem_u32(const void* p) {
    uint32_t a;
    asm("{ .reg .u64 t; cvta.to.shared.u64 t, %1; cvt.u32.u64 %0, t; }" : "=r"(a) : "l"(p));
    return a;
}

// XOR-swizzled byte offset inside a [128 rows][128 cols] bf16 tile (256B/row).
// 16B granule index XORed with (row & 7) -> conflict-free ldmatrix.
__device__ __forceinline__ uint32_t swoff(int row, int col) {
    return (uint32_t)row * 256u
         + ((uint32_t)(((col >> 3) ^ (row & 7)) & 15) << 4)
         + ((uint32_t)(col & 7) << 1);
}

#define LDM4(r0, r1, r2, r3, a) \
    asm volatile("ldmatrix.sync.aligned.m8n8.x4.shared.b16 {%0,%1,%2,%3}, [%4];" \
        : "=r"(r0), "=r"(r1), "=r"(r2), "=r"(r3) : "r"(a))

#define MMA16(c, a, b0, b1) \
    asm volatile("mma.sync.aligned.m16n8k16.row.col.f32.bf16.bf16.f32 " \
        "{%0,%1,%2,%3},{%4,%5,%6,%7},{%8,%9},{%0,%1,%2,%3};" \
        : "+f"((c)[0]), "+f"((c)[1]), "+f"((c)[2]), "+f"((c)[3]) \
        : "r"((a)[0]), "r"((a)[1]), "r"((a)[2]), "r"((a)[3]), "r"(b0), "r"(b1))

__device__ __forceinline__ void split4(float4 v, uint2& hi, uint2& lo) {
    __nv_bfloat16 hx = __float2bfloat16_rn(v.x), hy = __float2bfloat16_rn(v.y);
    __nv_bfloat16 hz = __float2bfloat16_rn(v.z), hw = __float2bfloat16_rn(v.w);
    float rx = v.x - __bfloat162float(hx), ry = v.y - __bfloat162float(hy);
    float rz = v.z - __bfloat162float(hz), rw = v.w - __bfloat162float(hw);
    __nv_bfloat162 H0; H0.x = hx; H0.y = hy;
    __nv_bfloat162 H1; H1.x = hz; H1.y = hw;
    __nv_bfloat162 L0 = __floats2bfloat162_rn(rx, ry);
    __nv_bfloat162 L1 = __floats2bfloat162_rn(rz, rw);
    hi.x = *(uint32_t*)&H0; hi.y = *(uint32_t*)&H1;
    lo.x = *(uint32_t*)&L0; lo.y = *(uint32_t*)&L1;
}

// fp32 global tile [nbase..nbase+128) x 128 -> split bf16 swizzled smem (256 thr)
__device__ __forceinline__ void conv_tile(const float* __restrict__ src, int nbase,
                                          char* ahi, char* alo) {
#pragma unroll 2
    for (int i = threadIdx.x; i < 4096; i += 256) {
        int row = i >> 5, c4 = i & 31;
        int node = nbase + row;
        float4 v = make_float4(0.f, 0.f, 0.f, 0.f);
        if (node < NN) v = ((const float4*)src)[node * 32 + c4];
        uint2 h, l;
        split4(v, h, l);
        uint32_t off = swoff(row, c4 * 4);
        *(uint2*)(ahi + off) = h;
        *(uint2*)(alo + off) = l;
    }
}

__device__ __forceinline__ void copyw(const __nv_bfloat16* src, char* dst) {
    for (int i = threadIdx.x; i < 2048; i += 256)
        ((uint4*)dst)[i] = ((const uint4*)src)[i];
}

// warp-tiled 3-term split GEMM: C[32x64] += (Ahi+Alo)@(Whi+Wlo) (dropping lo*lo)
// warp tile: rows wR..wR+31, cols wC..wC+63
__device__ __forceinline__ void gemm3(uint32_t ahi, uint32_t alo,
                                      uint32_t whi, uint32_t wlo,
                                      float C[2][8][4], int lane, int wR, int wC) {
    int arow = (lane & 7) + ((lane >> 3) & 1) * 8;
    int acolo = ((lane >> 4) & 1) * 8;
    int brow = (lane & 7) + ((lane >> 4) & 1) * 8;
    int bcolo = ((lane >> 3) & 1) * 8;
#pragma unroll
    for (int kk = 0; kk < 8; kk++) {
        int kbase = kk * 16;
        uint32_t ah[2][4], al[2][4];
#pragma unroll
        for (int mb = 0; mb < 2; mb++) {
            uint32_t oa = swoff(wR + mb * 16 + arow, kbase + acolo);
            LDM4(ah[mb][0], ah[mb][1], ah[mb][2], ah[mb][3], ahi + oa);
            LDM4(al[mb][0], al[mb][1], al[mb][2], al[mb][3], alo + oa);
        }
#pragma unroll
        for (int nbp = 0; nbp < 4; nbp++) {
            uint32_t ob = swoff(wC + nbp * 16 + brow, kbase + bcolo);
            uint32_t bh[4], bl[4];
            LDM4(bh[0], bh[1], bh[2], bh[3], whi + ob);
            LDM4(bl[0], bl[1], bl[2], bl[3], wlo + ob);
#pragma unroll
            for (int mb = 0; mb < 2; mb++) {
                MMA16(C[mb][2 * nbp],     ah[mb], bh[0], bh[1]);
                MMA16(C[mb][2 * nbp + 1], ah[mb], bh[2], bh[3]);
                MMA16(C[mb][2 * nbp],     ah[mb], bl[0], bl[1]);
                MMA16(C[mb][2 * nbp + 1], ah[mb], bl[2], bl[3]);
                MMA16(C[mb][2 * nbp],     al[mb], bh[0], bh[1]);
                MMA16(C[mb][2 * nbp + 1], al[mb], bh[2], bh[3]);
            }
        }
    }
}

// stage C frags into fp32 smem [128][132]
__device__ __forceinline__ void stageC(float* stg, float C[2][8][4], int lane, int wR, int wC) {
    int r0 = wR + (lane >> 2);
    int c0 = wC + (lane & 3) * 2;
#pragma unroll
    for (int mb = 0; mb < 2; mb++) {
#pragma unroll
        for (int nb = 0; nb < 8; nb++) {
            int row = r0 + mb * 16;
            int col = c0 + nb * 8;
            *(float2*)(stg + row * 132 + col) = make_float2(C[mb][nb][0], C[mb][nb][1]);
            *(float2*)(stg + (row + 8) * 132 + col) = make_float2(C[mb][nb][2], C[mb][nb][3]);
        }
    }
}

// ===================== setup kernels =====================
__global__ void k_zero() {
    int i = blockIdx.x * blockDim.x + threadIdx.x;
    if (i < NN) g_deg[i] = 0;
    if (i < NG) g_cnti[i] = 0;
    if (i < NG * FD) { g_gm[i] = 0.f; g_p[i] = 0.f; }
}
__global__ void k_count(const int* __restrict__ ei, const int* __restrict__ batch) {
    int i = blockIdx.x * blockDim.x + threadIdx.x;
    if (i < NE) atomicAdd(&g_deg[ei[NE + i]], 1);
    if (i < NN) atomicAdd(&g_cnti[batch[i]], 1);
}
__global__ void k_scan1() {
    __shared__ int s[512];
    int i = blockIdx.x * 512 + threadIdx.x;
    int v = (i < NN) ? g_deg[i] : 0;
    s[threadIdx.x] = v;
    __syncthreads();
#pragma unroll
    for (int off = 1; off < 512; off <<= 1) {
        int t = (threadIdx.x >= off) ? s[threadIdx.x - off] : 0;
        __syncthreads();
        s[threadIdx.x] += t;
        __syncthreads();
    }
    if (i < NN) g_rowstart[i + 1] = s[threadIdx.x];
    if (threadIdx.x == 511) g_bsum[blockIdx.x] = s[511];
}
__global__ void k_scan2() {
    __shared__ int s[256];
    const int nb = (NN + 511) / 512;
    int v = (threadIdx.x < nb) ? g_bsum[threadIdx.x] : 0;
    s[threadIdx.x] = v;
    __syncthreads();
#pragma unroll
    for (int off = 1; off < 256; off <<= 1) {
        int t = (threadIdx.x >= off) ? s[threadIdx.x - off] : 0;
        __syncthreads();
        s[threadIdx.x] += t;
        __syncthreads();
    }
    g_bsum[threadIdx.x] = s[threadIdx.x] - v;
}
__global__ void k_scan3() {
    int i = blockIdx.x * blockDim.x + threadIdx.x;
    if (i >= NN) return;
    int r = g_rowstart[i + 1] + g_bsum[i >> 9];
    g_rowstart[i + 1] = r;
    g_cursor[i] = r - g_deg[i];
    g_degf[i] = fmaxf((float)g_deg[i], 1.f);
    if (i == 0) g_rowstart[0] = 0;
    if (i < NG) g_cntf[i] = fmaxf((float)g_cnti[i], 1.f);
}
__global__ void k_fill(const int* __restrict__ ei) {
    int e = blockIdx.x * blockDim.x + threadIdx.x;
    if (e >= NE) return;
    int src = ei[e];
    int dst = ei[NE + e];
    int pos = atomicAdd(&g_cursor[dst], 1);
    g_csrsrc[pos] = src;
}
__global__ void k_gather() {
    int gw = (blockIdx.x * blockDim.x + threadIdx.x) >> 5;
    int lane = threadIdx.x & 31;
    if (gw >= NN) return;
    int beg = g_rowstart[gw], end = g_rowstart[gw + 1];
    float4 acc = make_float4(0.f, 0.f, 0.f, 0.f);
    const float4* hv = (const float4*)g_h;
    int e = beg;
    for (; e + 4 <= end; e += 4) {
        int s0 = g_csrsrc[e], s1 = g_csrsrc[e + 1], s2 = g_csrsrc[e + 2], s3 = g_csrsrc[e + 3];
        float4 a0 = hv[s0 * 32 + lane];
        float4 a1 = hv[s1 * 32 + lane];
        float4 a2 = hv[s2 * 32 + lane];
        float4 a3 = hv[s3 * 32 + lane];
        acc.x += (a0.x + a1.x) + (a2.x + a3.x);
        acc.y += (a0.y + a1.y) + (a2.y + a3.y);
        acc.z += (a0.z + a1.z) + (a2.z + a3.z);
        acc.w += (a0.w + a1.w) + (a2.w + a3.w);
    }
    for (; e < end; ++e) {
        int s0 = g_csrsrc[e];
        float4 a0 = hv[s0 * 32 + lane];
        acc.x += a0.x; acc.y += a0.y; acc.z += a0.z; acc.w += a0.w;
    }
    float inv = 1.f / g_degf[gw];
    acc.x *= inv; acc.y *= inv; acc.z *= inv; acc.w *= inv;
    ((float4*)g_agg)[gw * 32 + lane] = acc;
}
__global__ void k_wc(const float* __restrict__ mdfW) {
    int i = blockIdx.x * blockDim.x + threadIdx.x;
    if (i < FD * FD) g_Wc[i] = mdfW[i] + mdfW[FD * FD + i];
}
// weight prep: transpose to [N,K], split hi/lo bf16, store in swizzled layout
__global__ void k_wprep(const float* __restrict__ Win, const float* __restrict__ sWl,
                        const float* __restrict__ sWr, const float* __restrict__ l1W,
                        const float* __restrict__ l2W) {
    int m = blockIdx.y;
    const float* src;
    if (m == 0)       src = Win;
    else if (m < 4)   src = sWl + (m - 1) * 16384;
    else if (m < 7)   src = sWr + (m - 4) * 16384;
    else if (m < 10)  src = l1W + (m - 7) * 16384;
    else if (m < 13)  src = l2W + (m - 10) * 16384;
    else              src = g_Wc;
    int idx = blockIdx.x * 256 + threadIdx.x;
    if (idx >= 16384) return;
    int n = idx >> 7, k = idx & 127;
    float v = src[k * 128 + n];          // transpose: B[n,k] = W[k,n]
    __nv_bfloat16 hi = __float2bfloat16_rn(v);
    float r = v - __bfloat162float(hi);
    __nv_bfloat16 lo = __float2bfloat16_rn(r);
    uint32_t e = swoff(n, k) >> 1;
    g_whi[m * 16384 + e] = hi;
    g_wlo[m * 16384 + e] = lo;
}

// ===================== GEMM kernels (HMMA, 256 thr, 128-node tiles) =====================
// dynamic smem (1024-aligned): A_HI@0(32K) A_LO@32K W0H@64K W0L@96K [W1H@128K W1L@160K]
// fp32 staging [128][132] (67.6KB) overlaps A region + spills 3.6KB into W0H (dead then)

// ---- input: h = [x|w] @ W_in + b_in ----
__global__ void __launch_bounds__(256, 1) k_input(
    const float* __restrict__ x, const float* __restrict__ w,
    const float* __restrict__ Win, const float* __restrict__ bin) {
    extern __shared__ char dsm[];
    __shared__ float s_b[128], s_wr[128];
    uint32_t base = smem_u32(dsm);
    uint32_t ab = (base + 1023) & ~1023u;
    char* aptr = dsm + (ab - base);
    int tid = threadIdx.x;
    int lane = tid & 31, wid = tid >> 5;
    int wR = (wid >> 1) * 32, wC = (wid & 1) * 64;
    if (tid < 128) { s_b[tid] = bin[tid]; s_wr[tid] = Win[128 * 128 + tid]; }
    copyw(g_whi, aptr + 65536);
    copyw(g_wlo, aptr + 98304);
    int nbase = blockIdx.x * 128;
    conv_tile(x, nbase, aptr, aptr + 32768);
    __syncthreads();
    float C[2][8][4];
#pragma unroll
    for (int a = 0; a < 2; a++)
#pragma unroll
        for (int b = 0; b < 8; b++)
#pragma unroll
            for (int c = 0; c < 4; c++) C[a][b][c] = 0.f;
    gemm3(ab, ab + 32768, ab + 65536, ab + 98304, C, lane, wR, wC);
    __syncthreads();
    float* stg = (float*)aptr;
    stageC(stg, C, lane, wR, wC);
    __syncthreads();
#pragma unroll 2
    for (int i = tid; i < 4096; i += 256) {
        int row = i >> 5, c4 = i & 31;
        int nd = nbase + row;
        if (nd < NN) {
            float wn = w[nd];
            float4 v = ((float4*)(stg + row * 132))[c4];
            float4 o;
            o.x = v.x + s_b[c4 * 4 + 0] + wn * s_wr[c4 * 4 + 0];
            o.y = v.y + s_b[c4 * 4 + 1] + wn * s_wr[c4 * 4 + 1];
            o.z = v.z + s_b[c4 * 4 + 2] + wn * s_wr[c4 * 4 + 2];
            o.w = v.w + s_b[c4 * 4 + 3] + wn * s_wr[c4 * 4 + 3];
            ((float4*)g_h)[nd * 32 + c4] = o;
        }
    }
}

// ---- sage: y1 = LN(agg@Wl + bl + h@Wr + h) ----
__global__ void __launch_bounds__(256, 1) k_sage(
    int wlm, int wrm, const float* __restrict__ bl,
    const float* __restrict__ lng, const float* __restrict__ lnb) {
    extern __shared__ char dsm[];
    __shared__ float s_b[128], s_g[128], s_e[128];
    uint32_t base = smem_u32(dsm);
    uint32_t ab = (base + 1023) & ~1023u;
    char* aptr = dsm + (ab - base);
    int tid = threadIdx.x;
    int lane = tid & 31, wid = tid >> 5;
    int wR = (wid >> 1) * 32, wC = (wid & 1) * 64;
    if (tid < 128) { s_b[tid] = bl[tid]; s_g[tid] = lng[tid]; s_e[tid] = lnb[tid]; }
    copyw(g_whi + wlm * 16384, aptr + 65536);
    copyw(g_wlo + wlm * 16384, aptr + 98304);
    copyw(g_whi + wrm * 16384, aptr + 131072);
    copyw(g_wlo + wrm * 16384, aptr + 163840);
    int nbase = blockIdx.x * 128;
    conv_tile(g_agg, nbase, aptr, aptr + 32768);
    __syncthreads();
    float C[2][8][4];
#pragma unroll
    for (int a = 0; a < 2; a++)
#pragma unroll
        for (int b = 0; b < 8; b++)
#pragma unroll
            for (int c = 0; c < 4; c++) C[a][b][c] = 0.f;
    gemm3(ab, ab + 32768, ab + 65536, ab + 98304, C, lane, wR, wC);
    __syncthreads();
    conv_tile(g_h, nbase, aptr, aptr + 32768);
    __syncthreads();
    gemm3(ab, ab + 32768, ab + 131072, ab + 163840, C, lane, wR, wC);
    __syncthreads();
    float* stg = (float*)aptr;
    stageC(stg, C, lane, wR, wC);
    __syncthreads();
    if (tid < 128) {
        int node = nbase + tid;
        int rn = node < NN ? node : NN - 1;
        const float4* hres = (const float4*)(g_h + (size_t)rn * 128);
        float* row = stg + tid * 132;
        float s = 0.f, q = 0.f;
#pragma unroll
        for (int c4 = 0; c4 < 32; c4++) {
            float4 h4 = hres[c4];
            float4 v = ((float4*)row)[c4];
            v.x += s_b[4 * c4 + 0] + h4.x;
            v.y += s_b[4 * c4 + 1] + h4.y;
            v.z += s_b[4 * c4 + 2] + h4.z;
            v.w += s_b[4 * c4 + 3] + h4.w;
            ((float4*)row)[c4] = v;
            s += v.x + v.y + v.z + v.w;
            q += v.x * v.x + v.y * v.y + v.z * v.z + v.w * v.w;
        }
        float mu = s * 0.0078125f;
        float var = q * 0.0078125f - mu * mu;
        float inv = rsqrtf(var + 1e-5f);
#pragma unroll
        for (int c4 = 0; c4 < 32; c4++) {
            float4 v = ((float4*)row)[c4];
            v.x = (v.x - mu) * inv * s_g[4 * c4 + 0] + s_e[4 * c4 + 0];
            v.y = (v.y - mu) * inv * s_g[4 * c4 + 1] + s_e[4 * c4 + 1];
            v.z = (v.z - mu) * inv * s_g[4 * c4 + 2] + s_e[4 * c4 + 2];
            v.w = (v.w - mu) * inv * s_g[4 * c4 + 3] + s_e[4 * c4 + 3];
            ((float4*)row)[c4] = v;
        }
    }
    __syncthreads();
#pragma unroll 2
    for (int i = tid; i < 4096; i += 256) {
        int row = i >> 5, c4 = i & 31;
        int nd = nbase + row;
        if (nd < NN) ((float4*)g_y1)[nd * 32 + c4] = ((float4*)(stg + row * 132))[c4];
    }
}

// ---- ffn: h = LN(elu(y1@W1+b1)@W2 + b2 + y1) ----
__global__ void __launch_bounds__(256, 1) k_ffn(
    int w1m, int w2m, const float* __restrict__ b1, const float* __restrict__ b2,
    const float* __restrict__ lng, const float* __restrict__ lnb) {
    extern __shared__ char dsm[];
    __shared__ float s_b1[128], s_b2[128], s_g[128], s_e[128];
    uint32_t base = smem_u32(dsm);
    uint32_t ab = (base + 1023) & ~1023u;
    char* aptr = dsm + (ab - base);
    int tid = threadIdx.x;
    int lane = tid & 31, wid = tid >> 5;
    int wR = (wid >> 1) * 32, wC = (wid & 1) * 64;
    if (tid < 128) {
        s_b1[tid] = b1[tid]; s_b2[tid] = b2[tid];
        s_g[tid] = lng[tid]; s_e[tid] = lnb[tid];
    }
    copyw(g_whi + w1m * 16384, aptr + 65536);
    copyw(g_wlo + w1m * 16384, aptr + 98304);
    copyw(g_whi + w2m * 16384, aptr + 131072);
    copyw(g_wlo + w2m * 16384, aptr + 163840);
    int nbase = blockIdx.x * 128;
    conv_tile(g_y1, nbase, aptr, aptr + 32768);
    __syncthreads();
    float C[2][8][4];
#pragma unroll
    for (int a = 0; a < 2; a++)
#pragma unroll
        for (int b = 0; b < 8; b++)
#pragma unroll
            for (int c = 0; c < 4; c++) C[a][b][c] = 0.f;
    gemm3(ab, ab + 32768, ab + 65536, ab + 98304, C, lane, wR, wC);
    __syncthreads();
    // elu(C + b1) -> split bf16 back into A buffers
    {
        char* ahi = aptr;
        char* alo = aptr + 32768;
        int r0 = wR + (lane >> 2);
        int c0 = wC + (lane & 3) * 2;
#pragma unroll
        for (int mb = 0; mb < 2; mb++) {
#pragma unroll
            for (int nb = 0; nb < 8; nb++) {
                int col = c0 + nb * 8;
#pragma unroll
                for (int h = 0; h < 2; h++) {
                    int row = r0 + mb * 16 + h * 8;
                    float t0 = C[mb][nb][2 * h + 0] + s_b1[col];
                    float t1 = C[mb][nb][2 * h + 1] + s_b1[col + 1];
                    t0 = t0 > 0.f ? t0 : expm1f(t0);
                    t1 = t1 > 0.f ? t1 : expm1f(t1);
                    __nv_bfloat16 h0 = __float2bfloat16_rn(t0);
                    __nv_bfloat16 h1 = __float2bfloat16_rn(t1);
                    __nv_bfloat162 HP; HP.x = h0; HP.y = h1;
                    __nv_bfloat162 LP = __floats2bfloat162_rn(t0 - __bfloat162float(h0),
                                                              t1 - __bfloat162float(h1));
                    uint32_t off = swoff(row, col);
                    *(uint32_t*)(ahi + off) = *(uint32_t*)&HP;
                    *(uint32_t*)(alo + off) = *(uint32_t*)&LP;
                }
            }
        }
    }
    __syncthreads();
#pragma unroll
    for (int a = 0; a < 2; a++)
#pragma unroll
        for (int b = 0; b < 8; b++)
#pragma unroll
            for (int c = 0; c < 4; c++) C[a][b][c] = 0.f;
    gemm3(ab, ab + 32768, ab + 131072, ab + 163840, C, lane, wR, wC);
    __syncthreads();
    float* stg = (float*)aptr;
    stageC(stg, C, lane, wR, wC);
    __syncthreads();
    if (tid < 128) {
        int node = nbase + tid;
        int rn = node < NN ? node : NN - 1;
        const float4* yres = (const float4*)(g_y1 + (size_t)rn * 128);
        float* row = stg + tid * 132;
        float s = 0.f, q = 0.f;
#pragma unroll
        for (int c4 = 0; c4 < 32; c4++) {
            float4 y4 = yres[c4];
            float4 v = ((float4*)row)[c4];
            v.x += s_b2[4 * c4 + 0] + y4.x;
            v.y += s_b2[4 * c4 + 1] + y4.y;
            v.z += s_b2[4 * c4 + 2] + y4.z;
            v.w += s_b2[4 * c4 + 3] + y4.w;
            ((float4*)row)[c4] = v;
            s += v.x + v.y + v.z + v.w;
            q += v.x * v.x + v.y * v.y + v.z * v.z + v.w * v.w;
        }
        float mu = s * 0.0078125f;
        float var = q * 0.0078125f - mu * mu;
        float inv = rsqrtf(var + 1e-5f);
#pragma unroll
        for (int c4 = 0; c4 < 32; c4++) {
            float4 v = ((float4*)row)[c4];
            v.x = (v.x - mu) * inv * s_g[4 * c4 + 0] + s_e[4 * c4 + 0];
            v.y = (v.y - mu) * inv * s_g[4 * c4 + 1] + s_e[4 * c4 + 1];
            v.z = (v.z - mu) * inv * s_g[4 * c4 + 2] + s_e[4 * c4 + 2];
            v.w = (v.w - mu) * inv * s_g[4 * c4 + 3] + s_e[4 * c4 + 3];
            ((float4*)row)[c4] = v;
        }
    }
    __syncthreads();
#pragma unroll 2
    for (int i = tid; i < 4096; i += 256) {
        int row = i >> 5, c4 = i & 31;
        int nd = nbase + row;
        if (nd < NN) ((float4*)g_h)[nd * 32 + c4] = ((float4*)(stg + row * 132))[c4];
    }
}

// ---- mdf: out = h@Wc + mdf_b - gW[batch]  (writes g_agg) ----
__global__ void __launch_bounds__(256, 1) k_mdf(
    const float* __restrict__ mb_b, const int* __restrict__ batch) {
    extern __shared__ char dsm[];
    __shared__ float s_b[128];
    uint32_t base = smem_u32(dsm);
    uint32_t ab = (base + 1023) & ~1023u;
    char* aptr = dsm + (ab - base);
    int tid = threadIdx.x;
    int lane = tid & 31, wid = tid >> 5;
    int wR = (wid >> 1) * 32, wC = (wid & 1) * 64;
    if (tid < 128) s_b[tid] = mb_b[tid];
    copyw(g_whi + 13 * 16384, aptr + 65536);
    copyw(g_wlo + 13 * 16384, aptr + 98304);
    int nbase = blockIdx.x * 128;
    conv_tile(g_h, nbase, aptr, aptr + 32768);
    __syncthreads();
    float C[2][8][4];
#pragma unroll
    for (int a = 0; a < 2; a++)
#pragma unroll
        for (int b = 0; b < 8; b++)
#pragma unroll
            for (int c = 0; c < 4; c++) C[a][b][c] = 0.f;
    gemm3(ab, ab + 32768, ab + 65536, ab + 98304, C, lane, wR, wC);
    __syncthreads();
    float* stg = (float*)aptr;
    stageC(stg, C, lane, wR, wC);
    __syncthreads();
#pragma unroll 2
    for (int i = tid; i < 4096; i += 256) {
        int row = i >> 5, c4 = i & 31;
        int nd = nbase + row;
        if (nd < NN) {
            int bg = batch[nd];
            float4 gw4 = ((const float4*)g_gw)[bg * 32 + c4];
            float4 v = ((float4*)(stg + row * 132))[c4];
            float4 o;
            o.x = v.x + s_b[c4 * 4 + 0] - gw4.x;
            o.y = v.y + s_b[c4 * 4 + 1] - gw4.y;
            o.z = v.z + s_b[c4 * 4 + 2] - gw4.z;
            o.w = v.w + s_b[c4 * 4 + 3] - gw4.w;
            ((float4*)g_agg)[nd * 32 + c4] = o;
        }
    }
}

// ===================== pooling / head =====================
__global__ void k_gmacc(const int* __restrict__ batch) {
    int i = blockIdx.x * blockDim.x + threadIdx.x;
    if (i >= NN * FD) return;
    int n = i >> 7, f = i & 127;
    atomicAdd(&g_gm[batch[n] * FD + f], g_h[i]);
}
__global__ void k_pacc(const int* __restrict__ batch) {
    int i = blockIdx.x * blockDim.x + threadIdx.x;
    if (i >= NN * FD) return;
    int n = i >> 7, f = i & 127;
    atomicAdd(&g_p[batch[n] * FD + f], g_agg[i]);
}
__global__ void k_gw(const float* __restrict__ mdfW) {
    __shared__ float s[128];
    int g = blockIdx.x, f = threadIdx.x;
    s[f] = g_gm[g * FD + f] / g_cntf[g];
    __syncthreads();
    const float* Wb = mdfW + FD * FD;
    float acc = 0.f;
#pragma unroll 4
    for (int k = 0; k < 128; k++) acc = fmaf(s[k], Wb[k * FD + f], acc);
    g_gw[g * FD + f] = acc;
}
__global__ void k_pool(const float* __restrict__ pg1, const float* __restrict__ pb1,
                       const float* __restrict__ W1, const float* __restrict__ b1,
                       const float* __restrict__ W2, const float* __restrict__ b2,
                       const float* __restrict__ pg2, const float* __restrict__ pb2,
                       float* __restrict__ out) {
    __shared__ float hh[128], tt[128], red[8];
    int g = blockIdx.x, f = threadIdx.x;
    int lane = f & 31, wp = f >> 5;
    float v = g_p[g * FD + f] / g_cntf[g];
    float s = v, q = v * v;
#pragma unroll
    for (int off = 16; off; off >>= 1) {
        s += __shfl_xor_sync(0xffffffffu, s, off);
        q += __shfl_xor_sync(0xffffffffu, q, off);
    }
    if (lane == 0) { red[wp] = s; red[4 + wp] = q; }
    __syncthreads();
    s = red[0] + red[1] + red[2] + red[3];
    q = red[4] + red[5] + red[6] + red[7];
    float mu = s * 0.0078125f;
    float var = q * 0.0078125f - mu * mu;
    float inv = rsqrtf(var + 1e-5f);
    float h0 = (v - mu) * inv * pg1[f] + pb1[f];
    __syncthreads();
    hh[f] = h0;
    __syncthreads();
    float a = 0.f;
#pragma unroll 4
    for (int k = 0; k < 128; k++) a = fmaf(hh[k], W1[k * FD + f], a);
    a += b1[f];
    a = a > 0.f ? a : expm1f(a);
    tt[f] = a;
    __syncthreads();
    float y = 0.f;
#pragma unroll 4
    for (int k = 0; k < 128; k++) y = fmaf(tt[k], W2[k * FD + f], y);
    y += b2[f];
    float v2 = y + h0;
    s = v2; q = v2 * v2;
#pragma unroll
    for (int off = 16; off; off >>= 1) {
        s += __shfl_xor_sync(0xffffffffu, s, off);
        q += __shfl_xor_sync(0xffffffffu, q, off);
    }
    if (lane == 0) { red[wp] = s; red[4 + wp] = q; }
    __syncthreads();
    s = red[0] + red[1] + red[2] + red[3];
    q = red[4] + red[5] + red[6] + red[7];
    mu = s * 0.0078125f;
    var = q * 0.0078125f - mu * mu;
    inv = rsqrtf(var + 1e-5f);
    out[g * FD + f] = (v2 - mu) * inv * pg2[f] + pb2[f];
}

// ===================== launcher =====================
extern "C" void kernel_launch(void* const* d_in, const int* in_sizes, int n_in,
                              void* d_out, int out_size) {
    const float* x    = (const float*)d_in[0];
    const float* w    = (const float*)d_in[1];
    const int*   ei   = (const int*)d_in[2];
    const int*   batch= (const int*)d_in[3];
    const float* Win  = (const float*)d_in[4];
    const float* bin  = (const float*)d_in[5];
    const float* sWl  = (const float*)d_in[6];
    const float* sbl  = (const float*)d_in[7];
    const float* sWr  = (const float*)d_in[8];
    const float* ln1g = (const float*)d_in[9];
    const float* ln1b = (const float*)d_in[10];
    const float* l1W  = (const float*)d_in[11];
    const float* l1b  = (const float*)d_in[12];
    const float* l2W  = (const float*)d_in[13];
    const float* l2b  = (const float*)d_in[14];
    const float* ln2g = (const float*)d_in[15];
    const float* ln2b = (const float*)d_in[16];
    const float* mdfW = (const float*)d_in[17];
    const float* mdfb = (const float*)d_in[18];
    const float* pg1  = (const float*)d_in[19];
    const float* pb1  = (const float*)d_in[20];
    const float* pW1  = (const float*)d_in[21];
    const float* pb1l = (const float*)d_in[22];
    const float* pW2  = (const float*)d_in[23];
    const float* pb2l = (const float*)d_in[24];
    const float* pg2  = (const float*)d_in[25];
    const float* pb2  = (const float*)d_in[26];

    const int SM_BIG = 1024 + 196608;   // A(64K) + 4 W bufs(128K) + align
    const int SM_SML = 1024 + 131072;   // A(64K) + 2 W bufs(64K) + align
    cudaFuncSetAttribute(k_input, cudaFuncAttributeMaxDynamicSharedMemorySize, SM_SML);
    cudaFuncSetAttribute(k_sage,  cudaFuncAttributeMaxDynamicSharedMemorySize, SM_BIG);
    cudaFuncSetAttribute(k_ffn,   cudaFuncAttributeMaxDynamicSharedMemorySize, SM_BIG);
    cudaFuncSetAttribute(k_mdf,   cudaFuncAttributeMaxDynamicSharedMemorySize, SM_SML);

    k_zero<<<512, 256>>>();
    k_count<<<(NE + 255) / 256, 256>>>(ei, batch);
    k_scan1<<<(NN + 511) / 512, 512>>>();
    k_scan2<<<1, 256>>>();
    k_scan3<<<(NN + 255) / 256, 256>>>();
    k_fill<<<(NE + 255) / 256, 256>>>(ei);

    k_wc<<<(FD * FD + 255) / 256, 256>>>(mdfW);
    k_wprep<<<dim3(64, 14), 256>>>(Win, sWl, sWr, l1W, l2W);

    k_input<<<NTILE, 256, SM_SML>>>(x, w, Win, bin);

    for (int l = 0; l < 3; l++) {
        k_gather<<<(NN * 32) / 256, 256>>>();
        k_sage<<<NTILE, 256, SM_BIG>>>(1 + l, 4 + l, sbl + l * FD, ln1g + l * FD, ln1b + l * FD);
        k_ffn<<<NTILE, 256, SM_BIG>>>(7 + l, 10 + l, l1b + l * FD, l2b + l * FD,
                                      ln2g + l * FD, ln2b + l * FD);
    }

    k_gmacc<<<(NN * FD + 255) / 256, 256>>>(batch);
    k_gw<<<NG, 128>>>(mdfW);
    k_mdf<<<NTILE, 256, SM_SML>>>(mdfb, batch);
    k_pacc<<<(NN * FD + 255) / 256, 256>>>(batch);
    k_pool<<<NG, 128>>>(pg1, pb1, pW1, pb1l, pW2, pb2l, pg2, pb2, (float*)d_out);
}